// round 16
// baseline (speedup 1.0000x reference)
#include <cuda_runtime.h>
#include <math.h>

#define DD 256   // feature dim D
#define SS 8     // memory slots S
#define MAXB 512
#define MAXT 256
#define TM 32    // rows per XW tile

typedef unsigned long long u64;

// ---- packed fp32x2 helpers (Blackwell; IEEE-identical to scalar fp32) ----
__device__ __forceinline__ u64 pack2(float lo, float hi) {
    u64 r; asm("mov.b64 %0, {%1, %2};" : "=l"(r) : "f"(lo), "f"(hi)); return r;
}
__device__ __forceinline__ void fma2(u64& acc, u64 a, u64 b) {
    asm("fma.rn.f32x2 %0, %1, %2, %0;" : "+l"(acc) : "l"(a), "l"(b));
}
__device__ __forceinline__ float2 unpack2(u64 v) {
    float lo, hi; asm("mov.b64 {%0, %1}, %2;" : "=f"(lo), "=f"(hi) : "l"(v));
    return make_float2(lo, hi);
}

// Multi-value butterfly: reduce 8 per-lane values over 32 lanes in 9 shuffles.
// Lane L ends holding the warp sum of slot s = bits[2:4]; (L&3)==0 lanes write.
__device__ __forceinline__ void butterfly8(float p[SS], int lane,
                                           float red[SS][8], int warp) {
    const bool h16 = (lane & 16) != 0;
#pragma unroll
    for (int j = 0; j < 4; ++j) {
        const float send = h16 ? p[j] : p[j + 4];
        const float keep = h16 ? p[j + 4] : p[j];
        p[j] = keep + __shfl_xor_sync(0xffffffffu, send, 16);
    }
    const bool h8 = (lane & 8) != 0;
#pragma unroll
    for (int j = 0; j < 2; ++j) {
        const float send = h8 ? p[j] : p[j + 2];
        const float keep = h8 ? p[j + 2] : p[j];
        p[j] = keep + __shfl_xor_sync(0xffffffffu, send, 8);
    }
    const bool h4 = (lane & 4) != 0;
    {
        const float send = h4 ? p[0] : p[1];
        const float keep = h4 ? p[1] : p[0];
        p[0] = keep + __shfl_xor_sync(0xffffffffu, send, 4);
    }
    float v = p[0];
    v += __shfl_xor_sync(0xffffffffu, v, 2);
    v += __shfl_xor_sync(0xffffffffu, v, 1);
    if ((lane & 3) == 0) red[lane >> 2][warp] = v;
}

// Legal scratch: __device__ globals.
__device__ float g_xw[(size_t)MAXB * MAXT * DD];         // x@W     [B,T,D]
__device__ float g_gk[(size_t)MAXB * MAXT * SS];         // x@keys^T[B,T,S]
__device__ int   g_perm[MAXB];                           // batches by desc len

// ---------------------------------------------------------------------------
// Counting sort: g_perm = batch indices in descending length order (LPT).
// ---------------------------------------------------------------------------
__global__ void sort_kernel(const int* __restrict__ lengths, int B, int T) {
    __shared__ int cnt[MAXT + 1];
    __shared__ int off[MAXT + 1];
    const int tid = threadIdx.x;
    for (int i = tid; i <= T; i += blockDim.x) cnt[i] = 0;
    __syncthreads();
    for (int b = tid; b < B; b += blockDim.x) atomicAdd(&cnt[lengths[b]], 1);
    __syncthreads();
    if (tid == 0) {
        int acc = 0;
        for (int l = T; l >= 1; --l) { off[l] = acc; acc += cnt[l]; }
    }
    __syncthreads();
    for (int b = tid; b < B; b += blockDim.x) {
        const int pos = atomicAdd(&off[lengths[b]], 1);
        g_perm[pos] = b;
    }
}

// ---------------------------------------------------------------------------
// Precompute XW[b,t,:] = x@W and GK[b,t,:] = x@keys^T for t < len[b].
// ---------------------------------------------------------------------------
__global__ __launch_bounds__(256) void xw_kernel(
    const float* __restrict__ inputs,   // [B,T,D]
    const int*   __restrict__ lengths,
    const float* __restrict__ W,        // [D,D]
    const float* __restrict__ keys,     // [S,D]
    int T)
{
    const int b  = blockIdx.y;
    const int t0 = blockIdx.x * TM;
    if (t0 >= lengths[b]) return;        // fully-masked tile: no work
    const int rows = min(TM, T - t0);

    __shared__ __align__(16) float As[DD][TM];   // transposed x-tile, 32KB
    const float* A = inputs + ((size_t)b * T + t0) * DD;
    const int tid = threadIdx.x;

    for (int i = tid; i < rows * (DD / 4); i += 256) {
        const int m = i / (DD / 4), d4 = i % (DD / 4);
        const float4 v = *(const float4*)&A[(size_t)m * DD + d4 * 4];
        As[d4 * 4 + 0][m] = v.x;
        As[d4 * 4 + 1][m] = v.y;
        As[d4 * 4 + 2][m] = v.z;
        As[d4 * 4 + 3][m] = v.w;
    }
    __syncthreads();

    const int e = tid;
    u64 acc2[TM / 2];
#pragma unroll
    for (int m = 0; m < TM / 2; ++m) acc2[m] = 0ull;
    const float* wp = W + e;
#pragma unroll 2
    for (int d = 0; d < DD; ++d) {
        const float w = *wp; wp += DD;
        const u64 ww = pack2(w, w);
        const ulonglong2* ap = (const ulonglong2*)&As[d][0];
#pragma unroll
        for (int m4 = 0; m4 < TM / 4; ++m4) {
            const ulonglong2 a = ap[m4];
            fma2(acc2[m4 * 2 + 0], a.x, ww);
            fma2(acc2[m4 * 2 + 1], a.y, ww);
        }
    }
    float* o = g_xw + ((size_t)b * T + t0) * DD + e;
    for (int m = 0; m < rows; ++m) {
        const float2 f = unpack2(acc2[m >> 1]);
        o[(size_t)m * DD] = (m & 1) ? f.y : f.x;
    }

    // GK tail: 32 rows x 8 slots = 256 dot products, one per thread.
    {
        const int m = tid >> 3, s = tid & 7;
        if (m < rows) {
            const float* kp = keys + s * DD;
            float v = 0.f;
#pragma unroll 4
            for (int d = 0; d < DD; ++d) v = fmaf(As[d][m], kp[d], v);
            g_gk[((size_t)b * T + t0 + m) * SS + s] = v;
        }
    }
}

// ---------------------------------------------------------------------------
// Recurrence (R15 champion + r-finalize moved off the critical path):
// one CTA of 256 threads per batch (perm order). Raw state h[8] in registers
// (duplicated in SMEM stdup for the GEMM). Gate partials for step t+1 are
// butterflied at the END of phase B of step t into red1[(t+1)&1]. Norm
// partials go to red2[(t+1)&1] (parity-buffered); the r-finalize now runs
// INSIDE phase B (after S1) next to the ls-finalize, so nothing but 4 scalar
// loads sits between S2 and the next GEMM. red2[0] is primed to 0.125/warp so
// the step-0 finalize yields exactly r = 1. GEMM identical to champion:
// thread (q = tid>>6, c = tid&63) computes cols {2c, 2c+1, 2c+128, 2c+129}
// over d in [64q, 64q+64); per iter 2 LDG.64 + 4 LDS.128 + 16 FMA2, unroll 4.
// Thread finalizes col e = [2c,2c+1,2c+128,2c+129][q]; other 3 donated via
// SMEM under S1. kv in registers; 2 barriers/step; occ-2.
// ---------------------------------------------------------------------------
__global__ __launch_bounds__(256, 2) void dm_kernel(
    const float* __restrict__ inputs,
    const int*   __restrict__ lengths,
    const float* __restrict__ keys,
    const float* __restrict__ U,
    const float* __restrict__ V,
    const float* __restrict__ gate_bias,
    const float* __restrict__ state_bias,
    float*       __restrict__ out,
    int T)
{
    const int b    = g_perm[blockIdx.x];
    const int tid  = threadIdx.x;
    const int q    = tid >> 6;          // d-quarter
    const int c    = tid & 63;          // column-pair base
    const int e    = 2 * c + (q & 1) + (q >> 1) * 128;  // finalized column
    const int lane = tid & 31;
    const int warp = tid >> 5;
    const int sl    = lane & 7;         // slot this lane finalizes
    const int lbase = lane & 24;        // shuffle-broadcast group base

    // stdup row padded to 10 u64 (80B) -> 16B-aligned rows, mild banking
    __shared__ __align__(16) u64   stdup[DD][SS + 2];   // dup raw h  (20KB)
    __shared__ __align__(16) float buf[3][DD][SS];      // donations  (24KB)
    __shared__ __align__(16) float red1[2][SS][8];      // gate partials x2
    __shared__ __align__(16) float red2[2][SS][8];      // norm partials x2

    float h[SS];                        // raw state, loop-carried registers
#pragma unroll
    for (int s = 0; s < SS; ++s) {
        h[s] = keys[s * DD + e];
        stdup[e][s] = pack2(h[s], h[s]);  // init state = keys (raw, r=1)
    }
    // prime red2[0] so the step-0 r-finalize yields n2 = 8*0.125 = 1 -> r = 1
    if (tid < SS * 8) red2[0][tid >> 3][tid & 7] = 0.125f;
    __syncthreads();

    // ---- kv[s] = sum_d keys[s][d]*V[d][e] + sbias[e] (registers) ----
    float kv[SS];
    {
        float a[SS];
#pragma unroll
        for (int s = 0; s < SS; ++s) a[s] = 0.f;
        const float* vp = V + e;
#pragma unroll 4
        for (int d = 0; d < DD; ++d) {
            const float v = *vp; vp += DD;
            const ulonglong2 p01 = *(const ulonglong2*)&stdup[d][0];
            const ulonglong2 p23 = *(const ulonglong2*)&stdup[d][2];
            const ulonglong2 p45 = *(const ulonglong2*)&stdup[d][4];
            const ulonglong2 p67 = *(const ulonglong2*)&stdup[d][6];
            a[0] = fmaf(unpack2(p01.x).x, v, a[0]);
            a[1] = fmaf(unpack2(p01.y).x, v, a[1]);
            a[2] = fmaf(unpack2(p23.x).x, v, a[2]);
            a[3] = fmaf(unpack2(p23.y).x, v, a[3]);
            a[4] = fmaf(unpack2(p45.x).x, v, a[4]);
            a[5] = fmaf(unpack2(p45.y).x, v, a[5]);
            a[6] = fmaf(unpack2(p67.x).x, v, a[6]);
            a[7] = fmaf(unpack2(p67.y).x, v, a[7]);
        }
        const float sb = state_bias[e];
#pragma unroll
        for (int s = 0; s < SS; ++s) kv[s] = a[s] + sb;
    }

    const int   len   = lengths[b];
    const float gbias = gate_bias[0];
    const float* xb  = inputs + (size_t)b * T * DD + e;
    const float* xwb = g_xw   + (size_t)b * T * DD + e;
    const float* gkb = g_gk   + (size_t)b * T * SS;
    const float* UA  = U + (size_t)(q * 64) * DD + 2 * c;        // cols 2c,2c+1
    const float* UB  = UA + 128;                                 // +128,+129

    // Preamble: gate partials for t = 0 (x_0 . keys-state), into red1[0].
    {
        const float xv0 = xb[0];
        float p[SS];
#pragma unroll
        for (int s = 0; s < SS; ++s) p[s] = xv0 * h[s];
        butterfly8(p, lane, red1[0], warp);
    }

    for (int t = 0; t < len; ++t) {
        // phase-B scalars for current t + next step's xv (GEMM hides latency)
        const int tn = (t + 1 < len) ? t + 1 : len - 1;
        const float xv_n  = xb [(size_t)tn * DD];
        const float xwv   = xwb[(size_t)t * DD];
        const float4 gk0  = *(const float4*)&gkb[(size_t)t * SS];
        const float4 gk1  = *(const float4*)&gkb[(size_t)t * SS + 4];

        // ---- GEMM: accA[s] = (col 2c, col 2c+1), accB[s] = (+128, +129) ----
        u64 accA[SS], accB[SS];
#pragma unroll
        for (int s = 0; s < SS; ++s) { accA[s] = 0ull; accB[s] = 0ull; }
        {
            const float* ua = UA;
            const float* ub = UB;
            const int d0 = q * 64;
#pragma unroll 4
            for (int dd = 0; dd < 64; ++dd) {
                const int d = d0 + dd;
                const u64 uA = *(const u64*)ua;  ua += DD;
                const u64 uB = *(const u64*)ub;  ub += DD;
                const ulonglong2 s01 = *(const ulonglong2*)&stdup[d][0];
                const ulonglong2 s23 = *(const ulonglong2*)&stdup[d][2];
                const ulonglong2 s45 = *(const ulonglong2*)&stdup[d][4];
                const ulonglong2 s67 = *(const ulonglong2*)&stdup[d][6];
                fma2(accA[0], s01.x, uA); fma2(accB[0], s01.x, uB);
                fma2(accA[1], s01.y, uA); fma2(accB[1], s01.y, uB);
                fma2(accA[2], s23.x, uA); fma2(accB[2], s23.x, uB);
                fma2(accA[3], s23.y, uA); fma2(accB[3], s23.y, uB);
                fma2(accA[4], s45.x, uA); fma2(accB[4], s45.x, uB);
                fma2(accA[5], s45.y, uA); fma2(accB[5], s45.y, uB);
                fma2(accA[6], s67.x, uA); fma2(accB[6], s67.x, uB);
                fma2(accA[7], s67.y, uA); fma2(accB[7], s67.y, uB);
            }
        }
        // unpack: per-column values for the 4 computed columns
        float vA0[SS], vA1[SS], vB0[SS], vB1[SS];
#pragma unroll
        for (int s = 0; s < SS; ++s) {
            const float2 fa = unpack2(accA[s]);
            const float2 fb = unpack2(accB[s]);
            vA0[s] = fa.x; vA1[s] = fa.y; vB0[s] = fb.x; vB1[s] = fb.y;
        }
        // donate 3 non-finalized columns: slot(k,q) = q - (q > k)
#pragma unroll
        for (int k = 0; k < 4; ++k) {
            if (k != q) {
                const int X  = 2 * c + (k & 1) + (k >> 1) * 128;
                const int ds = q - (q > k ? 1 : 0);
                const float* v = (k == 0) ? vA0 : (k == 1) ? vA1
                               : (k == 2) ? vB0 : vB1;
                *(float4*)&buf[ds][X][0] = make_float4(v[0], v[1], v[2], v[3]);
                *(float4*)&buf[ds][X][4] = make_float4(v[4], v[5], v[6], v[7]);
            }
        }
        __syncthreads();   // S1: red1/red2 + buf visible; stdup reads complete

        // ---- phase B: lane-parallel gate + norm finalize (slot sl) ----
        float ls[SS], r[SS];
        {
            const float4 u0 = *(const float4*)&red1[t & 1][sl][0];
            const float4 u1 = *(const float4*)&red1[t & 1][sl][4];
            const float lsv = ((u0.x + u0.y) + (u0.z + u0.w))
                            + ((u1.x + u1.y) + (u1.z + u1.w));
            const float4 v0 = *(const float4*)&red2[t & 1][sl][0];
            const float4 v1 = *(const float4*)&red2[t & 1][sl][4];
            const float n2 = ((v0.x + v0.y) + (v0.z + v0.w))
                           + ((v1.x + v1.y) + (v1.z + v1.w));
            const float rv = (n2 > 1e-24f) ? rsqrtf(n2) : 1e12f;
#pragma unroll
            for (int s = 0; s < SS; ++s) {
                ls[s] = __shfl_sync(0xffffffffu, lsv, lbase + s);
                r[s]  = __shfl_sync(0xffffffffu, rv,  lbase + s);
            }
        }
        // finalize own column e
        float accf[SS];
        {
            const float* own = (q == 0) ? vA0 : (q == 1) ? vA1
                             : (q == 2) ? vB0 : vB1;
#pragma unroll
            for (int s = 0; s < SS; ++s) accf[s] = own[s];
#pragma unroll
            for (int j = 0; j < 3; ++j) {
                const float4 r0 = *(const float4*)&buf[j][e][0];
                const float4 r1 = *(const float4*)&buf[j][e][4];
                accf[0] += r0.x; accf[1] += r0.y;
                accf[2] += r0.z; accf[3] += r0.w;
                accf[4] += r1.x; accf[5] += r1.y;
                accf[6] += r1.z; accf[7] += r1.w;
            }
        }
        const float gk[SS] = {gk0.x, gk0.y, gk0.z, gk0.w,
                              gk1.x, gk1.y, gk1.z, gk1.w};
        float qq[SS];
#pragma unroll
        for (int s = 0; s < SS; ++s) {
            const float logit = fmaf(r[s], ls[s], gk[s] + gbias);
            const float g = __fdividef(1.f, 1.f + __expf(-logit));
            const float pre = fmaf(r[s], accf[s], kv[s] + xwv);
            const float ht  = pre > 0.f ? pre : (__expf(pre) - 1.f);
            h[s] = fmaf(r[s], h[s], g * ht);    // new raw state (registers)
            qq[s] = h[s] * h[s];
        }
        {
            ulonglong2 w01 = {pack2(h[0], h[0]), pack2(h[1], h[1])};
            ulonglong2 w23 = {pack2(h[2], h[2]), pack2(h[3], h[3])};
            ulonglong2 w45 = {pack2(h[4], h[4]), pack2(h[5], h[5])};
            ulonglong2 w67 = {pack2(h[6], h[6]), pack2(h[7], h[7])};
            *(ulonglong2*)&stdup[e][0] = w01;
            *(ulonglong2*)&stdup[e][2] = w23;
            *(ulonglong2*)&stdup[e][4] = w45;
            *(ulonglong2*)&stdup[e][6] = w67;
        }
        butterfly8(qq, lane, red2[(t + 1) & 1], warp);  // norm partials
        // gate partials for step t+1, from registers (fused phase A)
        {
            float p[SS];
#pragma unroll
            for (int s = 0; s < SS; ++s) p[s] = xv_n * h[s];
            butterfly8(p, lane, red1[(t + 1) & 1], warp);
        }
        __syncthreads();   // S2: red1/red2 + stdup writes visible
    }

    // final r-finalize + epilogue straight from registers
    float rfin;
    {
        const float4 u0 = *(const float4*)&red2[len & 1][sl][0];
        const float4 u1 = *(const float4*)&red2[len & 1][sl][4];
        const float n2 = ((u0.x + u0.y) + (u0.z + u0.w))
                       + ((u1.x + u1.y) + (u1.z + u1.w));
        rfin = (n2 > 1e-24f) ? rsqrtf(n2) : 1e12f;
    }
    float* ob = out + (size_t)b * SS * DD + e;
#pragma unroll
    for (int s = 0; s < SS; ++s)
        ob[s * DD] = h[s] * __shfl_sync(0xffffffffu, rfin, lbase + s);
}

// ---------------------------------------------------------------------------
// Inputs: inputs, lengths, keys, U, V, W, gate_bias, state_bias. Out: [B,S,D].
// ---------------------------------------------------------------------------
extern "C" void kernel_launch(void* const* d_in, const int* in_sizes, int n_in,
                              void* d_out, int out_size) {
    const float* inputs     = (const float*)d_in[0];
    const int*   lengths    = (const int*)  d_in[1];
    const float* keys       = (const float*)d_in[2];
    const float* U          = (const float*)d_in[3];
    const float* V          = (const float*)d_in[4];
    const float* W          = (const float*)d_in[5];
    const float* gate_bias  = (const float*)d_in[6];
    const float* state_bias = (const float*)d_in[7];

    const int B = in_sizes[1];                 // lengths element count
    const int T = in_sizes[0] / (B * DD);      // inputs = B*T*D

    sort_kernel<<<1, 256>>>(lengths, B, T);
    xw_kernel<<<dim3((T + TM - 1) / TM, B), 256>>>(inputs, lengths, W, keys, T);
    dm_kernel<<<B, DD>>>(inputs, lengths, keys, U, V, gate_bias, state_bias,
                         (float*)d_out, T);
}

// round 17
// speedup vs baseline: 1.6580x; 1.6580x over previous
#include <cuda_runtime.h>
#include <math.h>

#define DD 256   // feature dim D
#define SS 8     // memory slots S
#define MAXB 512
#define MAXT 256
#define TM 32    // rows per XW tile

typedef unsigned long long u64;

// ---- packed fp32x2 helpers (Blackwell; IEEE-identical to scalar fp32) ----
__device__ __forceinline__ u64 pack2(float lo, float hi) {
    u64 r; asm("mov.b64 %0, {%1, %2};" : "=l"(r) : "f"(lo), "f"(hi)); return r;
}
__device__ __forceinline__ void fma2(u64& acc, u64 a, u64 b) {
    asm("fma.rn.f32x2 %0, %1, %2, %0;" : "+l"(acc) : "l"(a), "l"(b));
}
__device__ __forceinline__ float2 unpack2(u64 v) {
    float lo, hi; asm("mov.b64 {%0, %1}, %2;" : "=f"(lo), "=f"(hi) : "l"(v));
    return make_float2(lo, hi);
}

// Multi-value butterfly: reduce 8 per-lane values over 32 lanes in 9 shuffles.
// Lane L ends holding the warp sum of slot s = bits[2:4]; (L&3)==0 lanes write.
__device__ __forceinline__ void butterfly8(float p[SS], int lane,
                                           float red[SS][8], int warp) {
    const bool h16 = (lane & 16) != 0;
#pragma unroll
    for (int j = 0; j < 4; ++j) {
        const float send = h16 ? p[j] : p[j + 4];
        const float keep = h16 ? p[j + 4] : p[j];
        p[j] = keep + __shfl_xor_sync(0xffffffffu, send, 16);
    }
    const bool h8 = (lane & 8) != 0;
#pragma unroll
    for (int j = 0; j < 2; ++j) {
        const float send = h8 ? p[j] : p[j + 2];
        const float keep = h8 ? p[j + 2] : p[j];
        p[j] = keep + __shfl_xor_sync(0xffffffffu, send, 8);
    }
    const bool h4 = (lane & 4) != 0;
    {
        const float send = h4 ? p[0] : p[1];
        const float keep = h4 ? p[1] : p[0];
        p[0] = keep + __shfl_xor_sync(0xffffffffu, send, 4);
    }
    float v = p[0];
    v += __shfl_xor_sync(0xffffffffu, v, 2);
    v += __shfl_xor_sync(0xffffffffu, v, 1);
    if ((lane & 3) == 0) red[lane >> 2][warp] = v;
}

// Legal scratch: __device__ globals.
__device__ float g_xw[(size_t)MAXB * MAXT * DD];         // x@W     [B,T,D]
__device__ float g_gk[(size_t)MAXB * MAXT * SS];         // x@keys^T[B,T,S]
__device__ int   g_perm[MAXB];                           // batches by desc len
__device__ float g_kvb[SS * DD];                         // keys@V + state_bias

// ---------------------------------------------------------------------------
// Prep: block 0 = counting sort (g_perm, descending length, LPT);
//       blocks 1..8 = kvb row s-1: g_kvb[s][e] = keys[s]@V[:,e] + sbias[e].
// ---------------------------------------------------------------------------
__global__ void prep_kernel(const int* __restrict__ lengths, int B, int T,
                            const float* __restrict__ keys,
                            const float* __restrict__ V,
                            const float* __restrict__ state_bias) {
    if (blockIdx.x == 0) {
        __shared__ int cnt[MAXT + 1];
        __shared__ int off[MAXT + 1];
        const int tid = threadIdx.x;
        for (int i = tid; i <= T; i += blockDim.x) cnt[i] = 0;
        __syncthreads();
        for (int b = tid; b < B; b += blockDim.x) atomicAdd(&cnt[lengths[b]], 1);
        __syncthreads();
        if (tid == 0) {
            int acc = 0;
            for (int l = T; l >= 1; --l) { off[l] = acc; acc += cnt[l]; }
        }
        __syncthreads();
        for (int b = tid; b < B; b += blockDim.x) {
            const int pos = atomicAdd(&off[lengths[b]], 1);
            g_perm[pos] = b;
        }
    } else {
        const int s = blockIdx.x - 1;
        const int e = threadIdx.x;
        __shared__ float krow[DD];
        krow[e] = keys[s * DD + e];
        __syncthreads();
        float acc = state_bias[e];
#pragma unroll 4
        for (int d = 0; d < DD; ++d)
            acc = fmaf(krow[d], V[(size_t)d * DD + e], acc);
        g_kvb[s * DD + e] = acc;
    }
}

// ---------------------------------------------------------------------------
// Precompute XW[b,t,:] = x@W and GK[b,t,:] = x@keys^T for t < len[b].
// ---------------------------------------------------------------------------
__global__ __launch_bounds__(256) void xw_kernel(
    const float* __restrict__ inputs,   // [B,T,D]
    const int*   __restrict__ lengths,
    const float* __restrict__ W,        // [D,D]
    const float* __restrict__ keys,     // [S,D]
    int T)
{
    const int b  = blockIdx.y;
    const int t0 = blockIdx.x * TM;
    if (t0 >= lengths[b]) return;        // fully-masked tile: no work
    const int rows = min(TM, T - t0);

    __shared__ __align__(16) float As[DD][TM];   // transposed x-tile, 32KB
    const float* A = inputs + ((size_t)b * T + t0) * DD;
    const int tid = threadIdx.x;

    for (int i = tid; i < rows * (DD / 4); i += 256) {
        const int m = i / (DD / 4), d4 = i % (DD / 4);
        const float4 v = *(const float4*)&A[(size_t)m * DD + d4 * 4];
        As[d4 * 4 + 0][m] = v.x;
        As[d4 * 4 + 1][m] = v.y;
        As[d4 * 4 + 2][m] = v.z;
        As[d4 * 4 + 3][m] = v.w;
    }
    __syncthreads();

    const int e = tid;
    u64 acc2[TM / 2];
#pragma unroll
    for (int m = 0; m < TM / 2; ++m) acc2[m] = 0ull;
    const float* wp = W + e;
#pragma unroll 2
    for (int d = 0; d < DD; ++d) {
        const float w = *wp; wp += DD;
        const u64 ww = pack2(w, w);
        const ulonglong2* ap = (const ulonglong2*)&As[d][0];
#pragma unroll
        for (int m4 = 0; m4 < TM / 4; ++m4) {
            const ulonglong2 a = ap[m4];
            fma2(acc2[m4 * 2 + 0], a.x, ww);
            fma2(acc2[m4 * 2 + 1], a.y, ww);
        }
    }
    float* o = g_xw + ((size_t)b * T + t0) * DD + e;
    for (int m = 0; m < rows; ++m) {
        const float2 f = unpack2(acc2[m >> 1]);
        o[(size_t)m * DD] = (m & 1) ? f.y : f.x;
    }

    // GK tail: 32 rows x 8 slots = 256 dot products, one per thread.
    {
        const int m = tid >> 3, s = tid & 7;
        if (m < rows) {
            const float* kp = keys + s * DD;
            float v = 0.f;
#pragma unroll 4
            for (int d = 0; d < DD; ++d) v = fmaf(As[d][m], kp[d], v);
            g_gk[((size_t)b * T + t0 + m) * SS + s] = v;
        }
    }
}

// ---------------------------------------------------------------------------
// Recurrence (R15 champion; kv loaded from g_kvb instead of per-CTA GEMM):
// one CTA of 256 threads per batch (perm order). Raw state h[8] in REGISTERS
// (duplicated in SMEM stdup for the GEMM). Gate partials for step t+1 are
// butterflied at the END of phase B of step t into red1[(t+1)&1]; the only
// work between S2 and the next GEMM is the r-finalize (computed pre-GEMM,
// where the accumulator floats are dead -- phase B is the reg-pressure peak,
// nothing may be added there). GEMM: thread (q = tid>>6, c = tid&63) computes
// cols {2c, 2c+1, 2c+128, 2c+129} over d in [64q, 64q+64); per iter
// 2 LDG.64 + 4 LDS.128 + 16 FMA2, unroll 4. Thread finalizes col
// e = [2c,2c+1,2c+128,2c+129][q]; other 3 donated via SMEM under S1.
// kv in registers; lane-parallel finalize; 2 barriers/step; occ-2.
// ---------------------------------------------------------------------------
__global__ __launch_bounds__(256, 2) void dm_kernel(
    const float* __restrict__ inputs,
    const int*   __restrict__ lengths,
    const float* __restrict__ keys,
    const float* __restrict__ U,
    const float* __restrict__ gate_bias,
    float*       __restrict__ out,
    int T)
{
    const int b    = g_perm[blockIdx.x];
    const int tid  = threadIdx.x;
    const int q    = tid >> 6;          // d-quarter
    const int c    = tid & 63;          // column-pair base
    const int e    = 2 * c + (q & 1) + (q >> 1) * 128;  // finalized column
    const int lane = tid & 31;
    const int warp = tid >> 5;
    const int sl    = lane & 7;         // slot this lane finalizes
    const int lbase = lane & 24;        // shuffle-broadcast group base

    // stdup row padded to 10 u64 (80B) -> 16B-aligned rows, mild banking
    __shared__ __align__(16) u64   stdup[DD][SS + 2];   // dup raw h  (20KB)
    __shared__ __align__(16) float buf[3][DD][SS];      // donations  (24KB)
    __shared__ __align__(16) float red1[2][SS][8];      // gate partials x2
    __shared__ __align__(16) float red2[SS][8];         // norm partials

    float h[SS];                        // raw state, loop-carried registers
#pragma unroll
    for (int s = 0; s < SS; ++s) {
        h[s] = keys[s * DD + e];
        stdup[e][s] = pack2(h[s], h[s]);  // init state = keys (raw, r=1)
    }

    // kv[s] = precomputed keys@V + state_bias (coalesced loads)
    float kv[SS];
#pragma unroll
    for (int s = 0; s < SS; ++s) kv[s] = g_kvb[s * DD + e];

    const int   len   = lengths[b];
    const float gbias = gate_bias[0];
    const float* xb  = inputs + (size_t)b * T * DD + e;
    const float* xwb = g_xw   + (size_t)b * T * DD + e;
    const float* gkb = g_gk   + (size_t)b * T * SS;
    const float* UA  = U + (size_t)(q * 64) * DD + 2 * c;        // cols 2c,2c+1
    const float* UB  = UA + 128;                                 // +128,+129

    float r[SS];
#pragma unroll
    for (int s = 0; s < SS; ++s) r[s] = 1.f;

    // Preamble: gate partials for t = 0 (x_0 . keys-state), into red1[0].
    {
        const float xv0 = xb[0];
        float p[SS];
#pragma unroll
        for (int s = 0; s < SS; ++s) p[s] = xv0 * h[s];
        butterfly8(p, lane, red1[0], warp);
    }
    __syncthreads();   // stdup init + red1[0] visible

    for (int t = 0; t < len; ++t) {
        // ---- r-finalize from red2 (lane-parallel; skip at t = 0) ----
        if (t) {
            const float4 u0 = *(const float4*)&red2[sl][0];
            const float4 u1 = *(const float4*)&red2[sl][4];
            const float n2 = ((u0.x + u0.y) + (u0.z + u0.w))
                           + ((u1.x + u1.y) + (u1.z + u1.w));
            const float rv = (n2 > 1e-24f) ? rsqrtf(n2) : 1e12f;
#pragma unroll
            for (int s = 0; s < SS; ++s)
                r[s] = __shfl_sync(0xffffffffu, rv, lbase + s);
        }

        // phase-B scalars for current t + next step's xv (GEMM hides latency)
        const int tn = (t + 1 < len) ? t + 1 : len - 1;
        const float xv_n  = xb [(size_t)tn * DD];
        const float xwv   = xwb[(size_t)t * DD];
        const float4 gk0  = *(const float4*)&gkb[(size_t)t * SS];
        const float4 gk1  = *(const float4*)&gkb[(size_t)t * SS + 4];

        // ---- GEMM: accA[s] = (col 2c, col 2c+1), accB[s] = (+128, +129) ----
        u64 accA[SS], accB[SS];
#pragma unroll
        for (int s = 0; s < SS; ++s) { accA[s] = 0ull; accB[s] = 0ull; }
        {
            const float* ua = UA;
            const float* ub = UB;
            const int d0 = q * 64;
#pragma unroll 4
            for (int dd = 0; dd < 64; ++dd) {
                const int d = d0 + dd;
                const u64 uA = *(const u64*)ua;  ua += DD;
                const u64 uB = *(const u64*)ub;  ub += DD;
                const ulonglong2 s01 = *(const ulonglong2*)&stdup[d][0];
                const ulonglong2 s23 = *(const ulonglong2*)&stdup[d][2];
                const ulonglong2 s45 = *(const ulonglong2*)&stdup[d][4];
                const ulonglong2 s67 = *(const ulonglong2*)&stdup[d][6];
                fma2(accA[0], s01.x, uA); fma2(accB[0], s01.x, uB);
                fma2(accA[1], s01.y, uA); fma2(accB[1], s01.y, uB);
                fma2(accA[2], s23.x, uA); fma2(accB[2], s23.x, uB);
                fma2(accA[3], s23.y, uA); fma2(accB[3], s23.y, uB);
                fma2(accA[4], s45.x, uA); fma2(accB[4], s45.x, uB);
                fma2(accA[5], s45.y, uA); fma2(accB[5], s45.y, uB);
                fma2(accA[6], s67.x, uA); fma2(accB[6], s67.x, uB);
                fma2(accA[7], s67.y, uA); fma2(accB[7], s67.y, uB);
            }
        }
        // unpack: per-column values for the 4 computed columns
        float vA0[SS], vA1[SS], vB0[SS], vB1[SS];
#pragma unroll
        for (int s = 0; s < SS; ++s) {
            const float2 fa = unpack2(accA[s]);
            const float2 fb = unpack2(accB[s]);
            vA0[s] = fa.x; vA1[s] = fa.y; vB0[s] = fb.x; vB1[s] = fb.y;
        }
        // donate 3 non-finalized columns: slot(k,q) = q - (q > k)
#pragma unroll
        for (int k = 0; k < 4; ++k) {
            if (k != q) {
                const int X  = 2 * c + (k & 1) + (k >> 1) * 128;
                const int ds = q - (q > k ? 1 : 0);
                const float* v = (k == 0) ? vA0 : (k == 1) ? vA1
                               : (k == 2) ? vB0 : vB1;
                *(float4*)&buf[ds][X][0] = make_float4(v[0], v[1], v[2], v[3]);
                *(float4*)&buf[ds][X][4] = make_float4(v[4], v[5], v[6], v[7]);
            }
        }
        __syncthreads();   // S1: red1 + buf visible; all stdup reads complete

        // ---- phase B: lane-parallel gate finalize (slot sl per lane) ----
        float ls[SS];
        {
            const float4 u0 = *(const float4*)&red1[t & 1][sl][0];
            const float4 u1 = *(const float4*)&red1[t & 1][sl][4];
            const float lsv = ((u0.x + u0.y) + (u0.z + u0.w))
                            + ((u1.x + u1.y) + (u1.z + u1.w));
#pragma unroll
            for (int s = 0; s < SS; ++s)
                ls[s] = __shfl_sync(0xffffffffu, lsv, lbase + s);
        }
        // finalize own column e
        float accf[SS];
        {
            const float* own = (q == 0) ? vA0 : (q == 1) ? vA1
                             : (q == 2) ? vB0 : vB1;
#pragma unroll
            for (int s = 0; s < SS; ++s) accf[s] = own[s];
#pragma unroll
            for (int j = 0; j < 3; ++j) {
                const float4 r0 = *(const float4*)&buf[j][e][0];
                const float4 r1 = *(const float4*)&buf[j][e][4];
                accf[0] += r0.x; accf[1] += r0.y;
                accf[2] += r0.z; accf[3] += r0.w;
                accf[4] += r1.x; accf[5] += r1.y;
                accf[6] += r1.z; accf[7] += r1.w;
            }
        }
        const float gk[SS] = {gk0.x, gk0.y, gk0.z, gk0.w,
                              gk1.x, gk1.y, gk1.z, gk1.w};
        float qq[SS];
#pragma unroll
        for (int s = 0; s < SS; ++s) {
            const float logit = fmaf(r[s], ls[s], gk[s] + gbias);
            const float g = __fdividef(1.f, 1.f + __expf(-logit));
            const float pre = fmaf(r[s], accf[s], kv[s] + xwv);
            const float ht  = pre > 0.f ? pre : (__expf(pre) - 1.f);
            h[s] = fmaf(r[s], h[s], g * ht);    // new raw state (registers)
            qq[s] = h[s] * h[s];
        }
        {
            ulonglong2 w01 = {pack2(h[0], h[0]), pack2(h[1], h[1])};
            ulonglong2 w23 = {pack2(h[2], h[2]), pack2(h[3], h[3])};
            ulonglong2 w45 = {pack2(h[4], h[4]), pack2(h[5], h[5])};
            ulonglong2 w67 = {pack2(h[6], h[6]), pack2(h[7], h[7])};
            *(ulonglong2*)&stdup[e][0] = w01;
            *(ulonglong2*)&stdup[e][2] = w23;
            *(ulonglong2*)&stdup[e][4] = w45;
            *(ulonglong2*)&stdup[e][6] = w67;
        }
        butterfly8(qq, lane, red2, warp);       // norm partials
        // gate partials for step t+1, from registers (fused phase A)
        {
            float p[SS];
#pragma unroll
            for (int s = 0; s < SS; ++s) p[s] = xv_n * h[s];
            butterfly8(p, lane, red1[(t + 1) & 1], warp);
        }
        __syncthreads();   // S2: red2/red1 + stdup writes visible
    }

    // final r-finalize + epilogue straight from registers
    float rfin;
    {
        const float4 u0 = *(const float4*)&red2[sl][0];
        const float4 u1 = *(const float4*)&red2[sl][4];
        const float n2 = ((u0.x + u0.y) + (u0.z + u0.w))
                       + ((u1.x + u1.y) + (u1.z + u1.w));
        rfin = (n2 > 1e-24f) ? rsqrtf(n2) : 1e12f;
    }
    float* ob = out + (size_t)b * SS * DD + e;
#pragma unroll
    for (int s = 0; s < SS; ++s)
        ob[s * DD] = h[s] * __shfl_sync(0xffffffffu, rfin, lbase + s);
}

// ---------------------------------------------------------------------------
// Inputs: inputs, lengths, keys, U, V, W, gate_bias, state_bias. Out: [B,S,D].
// ---------------------------------------------------------------------------
extern "C" void kernel_launch(void* const* d_in, const int* in_sizes, int n_in,
                              void* d_out, int out_size) {
    const float* inputs     = (const float*)d_in[0];
    const int*   lengths    = (const int*)  d_in[1];
    const float* keys       = (const float*)d_in[2];
    const float* U          = (const float*)d_in[3];
    const float* V          = (const float*)d_in[4];
    const float* W          = (const float*)d_in[5];
    const float* gate_bias  = (const float*)d_in[6];
    const float* state_bias = (const float*)d_in[7];

    const int B = in_sizes[1];                 // lengths element count
    const int T = in_sizes[0] / (B * DD);      // inputs = B*T*D

    prep_kernel<<<1 + SS, 256>>>(lengths, B, T, keys, V, state_bias);
    xw_kernel<<<dim3((T + TM - 1) / TM, B), 256>>>(inputs, lengths, W, keys, T);
    dm_kernel<<<B, DD>>>(inputs, lengths, keys, U, gate_bias, (float*)d_out, T);
}